// round 1
// baseline (speedup 1.0000x reference)
#include <cuda_runtime.h>

typedef unsigned long long ULL;

__device__ __forceinline__ ULL pack2(float a, float b){
  ULL u; asm("mov.b64 %0, {%1, %2};" : "=l"(u) : "f"(a), "f"(b)); return u;
}
__device__ __forceinline__ float hsum2(ULL a){
  float lo, hi; asm("mov.b64 {%0, %1}, %2;" : "=f"(lo), "=f"(hi) : "l"(a));
  return lo + hi;
}
#define FMA2(d, a, b, c) asm("fma.rn.f32x2 %0, %1, %2, %3;" : "=l"(d) : "l"(a), "l"(b), "l"(c))

__device__ __forceinline__ float sigf(float x){
  return __fdividef(1.f, 1.f + __expf(-x));
}
__device__ __forceinline__ float tanhf_fast(float x){
  x = fminf(15.f, fmaxf(-15.f, x));
  float e = __expf(2.f * x);
  return __fdividef(e - 1.f, e + 1.f);
}

#define LSEQ 4096
#define HH   30
#define DEC  100

__global__ __launch_bounds__(32, 1) void seq2seq_kernel(
    const float* __restrict__ x,
    const float* __restrict__ eWih, const float* __restrict__ eWhh,
    const float* __restrict__ ebih, const float* __restrict__ ebhh,
    const float* __restrict__ dWih, const float* __restrict__ dWhh,
    const float* __restrict__ dbih, const float* __restrict__ dbhh,
    const float* __restrict__ lW,  const float* __restrict__ lb,
    float* __restrict__ out)
{
  __shared__ __align__(16) float xs[LSEQ];
  __shared__ __align__(16) float hb[2][32];
  __shared__ __align__(16) float dxb[2][32];
  __shared__ __align__(16) float dhb[2][32];
  __shared__ __align__(16) float hist[DEC * 32];

  const int t = threadIdx.x;
  const bool act = (t < HH);

  // stage x into shared (16KB), float4
  {
    const float4* x4 = (const float4*)x;
    float4* s4 = (float4*)xs;
    #pragma unroll 4
    for (int i = t; i < LSEQ / 4; i += 32) s4[i] = x4[i];
  }

  // ---------------- encoder weights -> packed registers ----------------
  ULL wr2[15], wz2[15], wn2[15];
  float wir = 0.f, wiz = 0.f, win = 0.f;
  float br = 0.f, bz = 0.f, bin_e = 0.f, bhn_e = 0.f;
  if (act){
    #pragma unroll
    for (int k = 0; k < 15; k++){
      wr2[k] = pack2(eWhh[(t         ) * HH + 2*k], eWhh[(t         ) * HH + 2*k + 1]);
      wz2[k] = pack2(eWhh[(t +   HH) * HH + 2*k], eWhh[(t +   HH) * HH + 2*k + 1]);
      wn2[k] = pack2(eWhh[(t + 2*HH) * HH + 2*k], eWhh[(t + 2*HH) * HH + 2*k + 1]);
    }
    wir = eWih[t]; wiz = eWih[t + HH]; win = eWih[t + 2*HH];
    br    = ebih[t]        + ebhh[t];
    bz    = ebih[t + HH]   + ebhh[t + HH];
    bin_e = ebih[t + 2*HH];
    bhn_e = ebhh[t + 2*HH];
  } else {
    #pragma unroll
    for (int k = 0; k < 15; k++){ wr2[k] = 0ull; wz2[k] = 0ull; wn2[k] = 0ull; }
  }
  __syncwarp();

  // ---------------- encoder recurrence: 4096 steps ----------------
  float h = 0.f;
  for (int s = 0; s < LSEQ; s++){
    float* b = hb[s & 1];
    b[t] = h;
    __syncwarp();
    const ULL* h2 = (const ULL*)b;
    ULL ar = 0ull, az = 0ull, an = 0ull;
    #pragma unroll
    for (int k = 0; k < 15; k++){
      ULL v = h2[k];
      FMA2(ar, wr2[k], v, ar);
      FMA2(az, wz2[k], v, az);
      FMA2(an, wn2[k], v, an);
    }
    float xv = xs[s];
    float r = sigf(fmaf(xv, wir, br) + hsum2(ar));
    float z = sigf(fmaf(xv, wiz, bz) + hsum2(az));
    float n = tanhf_fast(fmaf(xv, win, bin_e) + r * (hsum2(an) + bhn_e));
    h = fmaf(z, h - n, n);   // (1-z)*n + z*h
  }

  // ---------------- decoder weights -> packed registers ----------------
  ULL ir2[15], iz2[15], in2[15], hr2[15], hz2[15], hn2[15];
  float brd = 0.f, bzd = 0.f, bind = 0.f, bhnd = 0.f;
  if (act){
    #pragma unroll
    for (int k = 0; k < 15; k++){
      ir2[k] = pack2(dWih[(t         ) * HH + 2*k], dWih[(t         ) * HH + 2*k + 1]);
      iz2[k] = pack2(dWih[(t +   HH) * HH + 2*k], dWih[(t +   HH) * HH + 2*k + 1]);
      in2[k] = pack2(dWih[(t + 2*HH) * HH + 2*k], dWih[(t + 2*HH) * HH + 2*k + 1]);
      hr2[k] = pack2(dWhh[(t         ) * HH + 2*k], dWhh[(t         ) * HH + 2*k + 1]);
      hz2[k] = pack2(dWhh[(t +   HH) * HH + 2*k], dWhh[(t +   HH) * HH + 2*k + 1]);
      hn2[k] = pack2(dWhh[(t + 2*HH) * HH + 2*k], dWhh[(t + 2*HH) * HH + 2*k + 1]);
    }
    brd  = dbih[t]        + dbhh[t];
    bzd  = dbih[t + HH]   + dbhh[t + HH];
    bind = dbih[t + 2*HH];
    bhnd = dbhh[t + 2*HH];
  } else {
    #pragma unroll
    for (int k = 0; k < 15; k++){
      ir2[k] = 0ull; iz2[k] = 0ull; in2[k] = 0ull;
      hr2[k] = 0ull; hz2[k] = 0ull; hn2[k] = 0ull;
    }
  }

  // ---------------- decoder recurrence: 100 steps ----------------
  float hx = h;
  float hh = act ? 1.f : 0.f;   // carry = (h_enc, ones)
  for (int i = 0; i < DEC; i++){
    float* bx = dxb[i & 1];
    float* bh = dhb[i & 1];
    bx[t] = hx; bh[t] = hh;
    __syncwarp();
    const ULL* x2 = (const ULL*)bx;
    const ULL* h2 = (const ULL*)bh;
    ULL air = 0ull, aiz = 0ull, ain = 0ull, ahr = 0ull, ahz = 0ull, ahn = 0ull;
    #pragma unroll
    for (int k = 0; k < 15; k++){
      ULL xv2 = x2[k];
      ULL hv2 = h2[k];
      FMA2(air, ir2[k], xv2, air);
      FMA2(aiz, iz2[k], xv2, aiz);
      FMA2(ain, in2[k], xv2, ain);
      FMA2(ahr, hr2[k], hv2, ahr);
      FMA2(ahz, hz2[k], hv2, ahz);
      FMA2(ahn, hn2[k], hv2, ahn);
    }
    float r = sigf(hsum2(air) + hsum2(ahr) + brd);
    float z = sigf(hsum2(aiz) + hsum2(ahz) + bzd);
    float n = tanhf_fast(hsum2(ain) + bind + r * (hsum2(ahn) + bhnd));
    float nh = fmaf(z, hh - n, n);
    hist[i * 32 + t] = nh;
    hx = nh; hh = nh;
  }
  __syncwarp();

  // ---------------- linear head: out[j] = lW . hist[j] + lb ----------------
  float lb0 = lb[0];
  for (int j = t; j < DEC; j += 32){
    float s = lb0;
    #pragma unroll
    for (int k = 0; k < HH; k++)
      s = fmaf(lW[k], hist[j * 32 + k], s);
    out[j] = s;
  }
}

extern "C" void kernel_launch(void* const* d_in, const int* in_sizes, int n_in,
                              void* d_out, int out_size) {
  const float* x    = (const float*)d_in[0];
  const float* eWih = (const float*)d_in[1];
  const float* eWhh = (const float*)d_in[2];
  const float* ebih = (const float*)d_in[3];
  const float* ebhh = (const float*)d_in[4];
  const float* dWih = (const float*)d_in[5];
  const float* dWhh = (const float*)d_in[6];
  const float* dbih = (const float*)d_in[7];
  const float* dbhh = (const float*)d_in[8];
  const float* lW   = (const float*)d_in[9];
  const float* lb   = (const float*)d_in[10];
  float* out = (float*)d_out;

  seq2seq_kernel<<<1, 32>>>(x, eWih, eWhh, ebih, ebhh,
                            dWih, dWhh, dbih, dbhh, lW, lb, out);
}

// round 2
// speedup vs baseline: 1.1696x; 1.1696x over previous
#include <cuda_runtime.h>

typedef unsigned long long ULL;

__device__ __forceinline__ ULL pack2(float a, float b){
  ULL u; asm("mov.b64 %0, {%1, %2};" : "=l"(u) : "f"(a), "f"(b)); return u;
}
__device__ __forceinline__ float hsum2(ULL a){
  float lo, hi; asm("mov.b64 {%0, %1}, %2;" : "=f"(lo), "=f"(hi) : "l"(a));
  return lo + hi;
}
#define FMA2(d, a, b, c) asm("fma.rn.f32x2 %0, %1, %2, %3;" : "=l"(d) : "l"(a), "l"(b), "l"(c))
__device__ __forceinline__ ULL add2(ULL a, ULL b){
  ULL d; asm("add.rn.f32x2 %0, %1, %2;" : "=l"(d) : "l"(a), "l"(b)); return d;
}

__device__ __forceinline__ float tanhap(float x){
  float y; asm("tanh.approx.f32 %0, %1;" : "=f"(y) : "f"(x)); return y;
}
__device__ __forceinline__ float sigap(float x){
  return fmaf(0.5f, tanhap(0.5f * x), 0.5f);
}

#define LSEQ 4096
#define HH   30
#define DEC  100
#define FULLM 0xffffffffu

__global__ __launch_bounds__(32, 1) void seq2seq_kernel(
    const float* __restrict__ x,
    const float* __restrict__ eWih, const float* __restrict__ eWhh,
    const float* __restrict__ ebih, const float* __restrict__ ebhh,
    const float* __restrict__ dWih, const float* __restrict__ dWhh,
    const float* __restrict__ dbih, const float* __restrict__ dbhh,
    const float* __restrict__ lW,  const float* __restrict__ lb,
    float* __restrict__ out)
{
  __shared__ __align__(16) float xs[LSEQ];
  __shared__ __align__(16) float hist[DEC * 32];

  const int t = threadIdx.x;
  const bool act = (t < HH);

  // stage x into shared (16KB), float4
  {
    const float4* x4 = (const float4*)x;
    float4* s4 = (float4*)xs;
    #pragma unroll 4
    for (int i = t; i < LSEQ / 4; i += 32) s4[i] = x4[i];
  }

  // ---------------- encoder weights -> packed registers ----------------
  ULL wr2[15], wz2[15], wn2[15];
  float wir = 0.f, wiz = 0.f, win = 0.f;
  float br = 0.f, bz = 0.f, bin_e = 0.f, bhn_e = 0.f;
  if (act){
    #pragma unroll
    for (int k = 0; k < 15; k++){
      wr2[k] = pack2(eWhh[(t        ) * HH + 2*k], eWhh[(t        ) * HH + 2*k + 1]);
      wz2[k] = pack2(eWhh[(t +   HH) * HH + 2*k], eWhh[(t +   HH) * HH + 2*k + 1]);
      wn2[k] = pack2(eWhh[(t + 2*HH) * HH + 2*k], eWhh[(t + 2*HH) * HH + 2*k + 1]);
    }
    wir = eWih[t]; wiz = eWih[t + HH]; win = eWih[t + 2*HH];
    br    = ebih[t]        + ebhh[t];
    bz    = ebih[t + HH]   + ebhh[t + HH];
    bin_e = ebih[t + 2*HH];
    bhn_e = ebhh[t + 2*HH];
  } else {
    #pragma unroll
    for (int k = 0; k < 15; k++){ wr2[k] = 0ull; wz2[k] = 0ull; wn2[k] = 0ull; }
  }
  __syncwarp();

  // ---------------- encoder recurrence: 4096 steps ----------------
  float h = 0.f;
  for (int s = 0; s < LSEQ; s++){
    // x-gate precompute (off critical path)
    float xv = xs[s];
    float gxr = fmaf(xv, wir, br);
    float gxz = fmaf(xv, wiz, bz);
    float gxn = fmaf(xv, win, bin_e);

    // broadcast h via shfl (no smem, no barrier)
    ULL ar0=0, ar1=0, ar2=0, az0=0, az1=0, az2=0, an0=0, an1=0, an2=0;
    #pragma unroll
    for (int k = 0; k < 15; k++){
      float a = __shfl_sync(FULLM, h, 2*k);
      float b = __shfl_sync(FULLM, h, 2*k + 1);
      ULL v = pack2(a, b);
      if (k < 5)      { FMA2(ar0, wr2[k], v, ar0); FMA2(az0, wz2[k], v, az0); FMA2(an0, wn2[k], v, an0); }
      else if (k < 10){ FMA2(ar1, wr2[k], v, ar1); FMA2(az1, wz2[k], v, az1); FMA2(an1, wn2[k], v, an1); }
      else            { FMA2(ar2, wr2[k], v, ar2); FMA2(az2, wz2[k], v, az2); FMA2(an2, wn2[k], v, an2); }
    }
    float gr = hsum2(add2(add2(ar0, ar1), ar2));
    float gz = hsum2(add2(add2(az0, az1), az2));
    float gn = hsum2(add2(add2(an0, an1), an2));

    float r = sigap(gxr + gr);
    float z = sigap(gxz + gz);
    float n = tanhap(gxn + r * (gn + bhn_e));
    h = fmaf(z, h - n, n);   // (1-z)*n + z*h
  }

  // ---------------- decoder step 0 (x = h_enc, h = ones) ----------------
  // Broadcast h_enc once into a local array
  float hv[HH];
  #pragma unroll
  for (int k = 0; k < HH; k++) hv[k] = __shfl_sync(FULLM, h, k);

  float brd = 0.f, bzd = 0.f, bind = 0.f, bhnd = 0.f;
  if (act){
    brd  = dbih[t]        + dbhh[t];
    bzd  = dbih[t + HH]   + dbhh[t + HH];
    bind = dbih[t + 2*HH];
    bhnd = dbhh[t + 2*HH];
  }

  if (act){
    float gir = 0.f, giz = 0.f, gin = 0.f, sr = 0.f, sz = 0.f, sn = 0.f;
    #pragma unroll
    for (int k = 0; k < HH; k++){
      float hk = hv[k];
      gir = fmaf(dWih[(t        ) * HH + k], hk, gir);
      giz = fmaf(dWih[(t +   HH) * HH + k], hk, giz);
      gin = fmaf(dWih[(t + 2*HH) * HH + k], hk, gin);
      sr += dWhh[(t        ) * HH + k];
      sz += dWhh[(t +   HH) * HH + k];
      sn += dWhh[(t + 2*HH) * HH + k];
    }
    float r = sigap(gir + sr + brd);
    float z = sigap(giz + sz + bzd);
    float n = tanhap(gin + bind + r * (sn + bhnd));
    h = fmaf(z, 1.f - n, n);   // previous h is ones
  } else {
    h = 0.f;
  }
  hist[0 * 32 + t] = h;

  // ---------------- decoder weights (pre-summed r/z) -> packed registers ----------------
  ULL wsr2[15], wsz2[15], win2[15], whn2[15];
  if (act){
    #pragma unroll
    for (int k = 0; k < 15; k++){
      wsr2[k] = pack2(dWih[(t        ) * HH + 2*k]     + dWhh[(t        ) * HH + 2*k],
                      dWih[(t        ) * HH + 2*k + 1] + dWhh[(t        ) * HH + 2*k + 1]);
      wsz2[k] = pack2(dWih[(t +   HH) * HH + 2*k]     + dWhh[(t +   HH) * HH + 2*k],
                      dWih[(t +   HH) * HH + 2*k + 1] + dWhh[(t +   HH) * HH + 2*k + 1]);
      win2[k] = pack2(dWih[(t + 2*HH) * HH + 2*k], dWih[(t + 2*HH) * HH + 2*k + 1]);
      whn2[k] = pack2(dWhh[(t + 2*HH) * HH + 2*k], dWhh[(t + 2*HH) * HH + 2*k + 1]);
    }
  } else {
    #pragma unroll
    for (int k = 0; k < 15; k++){ wsr2[k]=0ull; wsz2[k]=0ull; win2[k]=0ull; whn2[k]=0ull; }
  }

  // ---------------- decoder steps 1..99 (hx == hh == h) ----------------
  for (int i = 1; i < DEC; i++){
    ULL ar0=0, ar1=0, ar2=0, az0=0, az1=0, az2=0;
    ULL ai0=0, ai1=0, ai2=0, ah0=0, ah1=0, ah2=0;
    #pragma unroll
    for (int k = 0; k < 15; k++){
      float a = __shfl_sync(FULLM, h, 2*k);
      float b = __shfl_sync(FULLM, h, 2*k + 1);
      ULL v = pack2(a, b);
      if (k < 5)      { FMA2(ar0, wsr2[k], v, ar0); FMA2(az0, wsz2[k], v, az0);
                        FMA2(ai0, win2[k], v, ai0); FMA2(ah0, whn2[k], v, ah0); }
      else if (k < 10){ FMA2(ar1, wsr2[k], v, ar1); FMA2(az1, wsz2[k], v, az1);
                        FMA2(ai1, win2[k], v, ai1); FMA2(ah1, whn2[k], v, ah1); }
      else            { FMA2(ar2, wsr2[k], v, ar2); FMA2(az2, wsz2[k], v, az2);
                        FMA2(ai2, win2[k], v, ai2); FMA2(ah2, whn2[k], v, ah2); }
    }
    float grs = hsum2(add2(add2(ar0, ar1), ar2));
    float gzs = hsum2(add2(add2(az0, az1), az2));
    float gin = hsum2(add2(add2(ai0, ai1), ai2));
    float ghn = hsum2(add2(add2(ah0, ah1), ah2));

    float r = sigap(grs + brd);
    float z = sigap(gzs + bzd);
    float n = tanhap(gin + bind + r * (ghn + bhnd));
    h = fmaf(z, h - n, n);
    hist[i * 32 + t] = h;
  }
  __syncwarp();

  // ---------------- linear head: out[j] = lW . hist[j] + lb ----------------
  float lb0 = lb[0];
  for (int j = t; j < DEC; j += 32){
    float s = lb0;
    #pragma unroll
    for (int k = 0; k < HH; k++)
      s = fmaf(lW[k], hist[j * 32 + k], s);
    out[j] = s;
  }
}

extern "C" void kernel_launch(void* const* d_in, const int* in_sizes, int n_in,
                              void* d_out, int out_size) {
  const float* x    = (const float*)d_in[0];
  const float* eWih = (const float*)d_in[1];
  const float* eWhh = (const float*)d_in[2];
  const float* ebih = (const float*)d_in[3];
  const float* ebhh = (const float*)d_in[4];
  const float* dWih = (const float*)d_in[5];
  const float* dWhh = (const float*)d_in[6];
  const float* dbih = (const float*)d_in[7];
  const float* dbhh = (const float*)d_in[8];
  const float* lW   = (const float*)d_in[9];
  const float* lb   = (const float*)d_in[10];
  float* out = (float*)d_out;

  seq2seq_kernel<<<1, 32>>>(x, eWih, eWhh, ebih, ebhh,
                            dWih, dWhh, dbih, dbhh, lW, lb, out);
}

// round 3
// speedup vs baseline: 1.3408x; 1.1464x over previous
#include <cuda_runtime.h>

typedef unsigned long long ULL;

__device__ __forceinline__ ULL pack2(float a, float b){
  ULL u; asm("mov.b64 %0, {%1, %2};" : "=l"(u) : "f"(a), "f"(b)); return u;
}
__device__ __forceinline__ float hsum2(ULL a){
  union { ULL u; float2 f; } c; c.u = a;
  return c.f.x + c.f.y;
}
#define FMA2(d, a, b, c) asm("fma.rn.f32x2 %0, %1, %2, %3;" : "=l"(d) : "l"(a), "l"(b), "l"(c))
__device__ __forceinline__ ULL add2(ULL a, ULL b){
  ULL d; asm("add.rn.f32x2 %0, %1, %2;" : "=l"(d) : "l"(a), "l"(b)); return d;
}

__device__ __forceinline__ float tanhap(float x){
  float y; asm("tanh.approx.f32 %0, %1;" : "=f"(y) : "f"(x)); return y;
}
__device__ __forceinline__ float sigap(float x){
  return fmaf(0.5f, tanhap(0.5f * x), 0.5f);
}

#define LSEQ 4096
#define HH   30
#define DEC  100
#define FULLM 0xffffffffu

__global__ __launch_bounds__(32, 1) void seq2seq_kernel(
    const float* __restrict__ x,
    const float* __restrict__ eWih, const float* __restrict__ eWhh,
    const float* __restrict__ ebih, const float* __restrict__ ebhh,
    const float* __restrict__ dWih, const float* __restrict__ dWhh,
    const float* __restrict__ dbih, const float* __restrict__ dbhh,
    const float* __restrict__ lW,  const float* __restrict__ lb,
    float* __restrict__ out)
{
  __shared__ __align__(16) float xs[LSEQ + 4];
  __shared__ __align__(16) float hb[2][32];
  __shared__ __align__(16) float db[2][32];
  __shared__ __align__(16) float hist[DEC * 32];

  const int t = threadIdx.x;
  const bool act = (t < HH);

  // stage x into shared (16KB), float4
  {
    const float4* x4 = (const float4*)x;
    float4* s4 = (float4*)xs;
    #pragma unroll 4
    for (int i = t; i < LSEQ / 4; i += 32) s4[i] = x4[i];
  }
  hb[0][t] = 0.f; hb[1][t] = 0.f;  // lanes 30/31 pairs must be defined

  // ---------------- encoder weights -> packed registers ----------------
  ULL wr2[15], wz2[15], wn2[15];
  float wir = 0.f, wiz = 0.f, win = 0.f;
  float br = 0.f, bz = 0.f, bin_e = 0.f, bhn_e = 0.f;
  if (act){
    #pragma unroll
    for (int k = 0; k < 15; k++){
      wr2[k] = pack2(eWhh[(t        ) * HH + 2*k], eWhh[(t        ) * HH + 2*k + 1]);
      wz2[k] = pack2(eWhh[(t +   HH) * HH + 2*k], eWhh[(t +   HH) * HH + 2*k + 1]);
      wn2[k] = pack2(eWhh[(t + 2*HH) * HH + 2*k], eWhh[(t + 2*HH) * HH + 2*k + 1]);
    }
    wir = eWih[t]; wiz = eWih[t + HH]; win = eWih[t + 2*HH];
    br    = ebih[t]        + ebhh[t];
    bz    = ebih[t + HH]   + ebhh[t + HH];
    bin_e = ebih[t + 2*HH];
    bhn_e = ebhh[t + 2*HH];
  } else {
    #pragma unroll
    for (int k = 0; k < 15; k++){ wr2[k] = 0ull; wz2[k] = 0ull; wn2[k] = 0ull; }
  }
  __syncwarp();

  // ---------------- encoder recurrence: 4096 steps ----------------
  float h = 0.f;
  float xv = xs[0];
  #pragma unroll 4
  for (int s = 0; s < LSEQ; s++){
    // x-gate precompute (off critical path)
    float gxr = fmaf(xv, wir, br);
    float gxz = fmaf(xv, wiz, bz);
    float gxn = fmaf(xv, win, bin_e);

    float* b = hb[s & 1];
    b[t] = h;
    __syncwarp();
    xv = xs[s + 1];           // prefetch next x (overread padded)

    // 8x LDS.128 broadcast of the 30-float hidden state
    ULL p[16];
    {
      const ulonglong2* b2 = (const ulonglong2*)b;
      #pragma unroll
      for (int q = 0; q < 8; q++){ ulonglong2 u = b2[q]; p[2*q] = u.x; p[2*q+1] = u.y; }
    }

    // r/z gates first so their transcendentals overlap the n accumulation
    ULL ar0=0, ar1=0, ar2=0, az0=0, az1=0, az2=0;
    #pragma unroll
    for (int k = 0; k < 15; k++){
      ULL v = p[k];
      if (k < 5)      { FMA2(ar0, wr2[k], v, ar0); FMA2(az0, wz2[k], v, az0); }
      else if (k < 10){ FMA2(ar1, wr2[k], v, ar1); FMA2(az1, wz2[k], v, az1); }
      else            { FMA2(ar2, wr2[k], v, ar2); FMA2(az2, wz2[k], v, az2); }
    }
    float r = sigap(gxr + hsum2(add2(add2(ar0, ar1), ar2)));
    float z = sigap(gxz + hsum2(add2(add2(az0, az1), az2)));

    ULL an0=0, an1=0, an2=0;
    #pragma unroll
    for (int k = 0; k < 15; k++){
      ULL v = p[k];
      if (k < 5)       FMA2(an0, wn2[k], v, an0);
      else if (k < 10) FMA2(an1, wn2[k], v, an1);
      else             FMA2(an2, wn2[k], v, an2);
    }
    float gn = hsum2(add2(add2(an0, an1), an2));

    float n = tanhap(gxn + r * (gn + bhn_e));
    h = fmaf(z, h - n, n);   // (1-z)*n + z*h
  }

  // ---------------- decoder step 0 (x = h_enc, h = ones) ----------------
  float hv[HH];
  #pragma unroll
  for (int k = 0; k < HH; k++) hv[k] = __shfl_sync(FULLM, h, k);

  float brd = 0.f, bzd = 0.f, bind = 0.f, bhnd = 0.f;
  if (act){
    brd  = dbih[t]        + dbhh[t];
    bzd  = dbih[t + HH]   + dbhh[t + HH];
    bind = dbih[t + 2*HH];
    bhnd = dbhh[t + 2*HH];
  }

  if (act){
    float gir = 0.f, giz = 0.f, gin = 0.f, sr = 0.f, sz = 0.f, sn = 0.f;
    #pragma unroll
    for (int k = 0; k < HH; k++){
      float hk = hv[k];
      gir = fmaf(dWih[(t        ) * HH + k], hk, gir);
      giz = fmaf(dWih[(t +   HH) * HH + k], hk, giz);
      gin = fmaf(dWih[(t + 2*HH) * HH + k], hk, gin);
      sr += dWhh[(t        ) * HH + k];
      sz += dWhh[(t +   HH) * HH + k];
      sn += dWhh[(t + 2*HH) * HH + k];
    }
    float r = sigap(gir + sr + brd);
    float z = sigap(giz + sz + bzd);
    float n = tanhap(gin + bind + r * (sn + bhnd));
    h = fmaf(z, 1.f - n, n);   // previous h is ones
  } else {
    h = 0.f;
  }
  hist[0 * 32 + t] = h;

  // ---------------- decoder weights (pre-summed r/z: hx==hh) --------------
  ULL wsr2[15], wsz2[15], win2[15], whn2[15];
  if (act){
    #pragma unroll
    for (int k = 0; k < 15; k++){
      wsr2[k] = pack2(dWih[(t        ) * HH + 2*k]     + dWhh[(t        ) * HH + 2*k],
                      dWih[(t        ) * HH + 2*k + 1] + dWhh[(t        ) * HH + 2*k + 1]);
      wsz2[k] = pack2(dWih[(t +   HH) * HH + 2*k]     + dWhh[(t +   HH) * HH + 2*k],
                      dWih[(t +   HH) * HH + 2*k + 1] + dWhh[(t +   HH) * HH + 2*k + 1]);
      win2[k] = pack2(dWih[(t + 2*HH) * HH + 2*k], dWih[(t + 2*HH) * HH + 2*k + 1]);
      whn2[k] = pack2(dWhh[(t + 2*HH) * HH + 2*k], dWhh[(t + 2*HH) * HH + 2*k + 1]);
    }
  } else {
    #pragma unroll
    for (int k = 0; k < 15; k++){ wsr2[k]=0ull; wsz2[k]=0ull; win2[k]=0ull; whn2[k]=0ull; }
  }
  db[0][t] = 0.f; db[1][t] = 0.f;

  // ---------------- decoder steps 1..99 (hx == hh == h) ----------------
  for (int i = 1; i < DEC; i++){
    float* b = db[i & 1];
    b[t] = h;
    __syncwarp();
    ULL p[16];
    {
      const ulonglong2* b2 = (const ulonglong2*)b;
      #pragma unroll
      for (int q = 0; q < 8; q++){ ulonglong2 u = b2[q]; p[2*q] = u.x; p[2*q+1] = u.y; }
    }
    ULL ar0=0, ar1=0, ar2=0, az0=0, az1=0, az2=0;
    #pragma unroll
    for (int k = 0; k < 15; k++){
      ULL v = p[k];
      if (k < 5)      { FMA2(ar0, wsr2[k], v, ar0); FMA2(az0, wsz2[k], v, az0); }
      else if (k < 10){ FMA2(ar1, wsr2[k], v, ar1); FMA2(az1, wsz2[k], v, az1); }
      else            { FMA2(ar2, wsr2[k], v, ar2); FMA2(az2, wsz2[k], v, az2); }
    }
    float r = sigap(hsum2(add2(add2(ar0, ar1), ar2)) + brd);
    float z = sigap(hsum2(add2(add2(az0, az1), az2)) + bzd);

    ULL ai0=0, ai1=0, ai2=0, ah0=0, ah1=0, ah2=0;
    #pragma unroll
    for (int k = 0; k < 15; k++){
      ULL v = p[k];
      if (k < 5)      { FMA2(ai0, win2[k], v, ai0); FMA2(ah0, whn2[k], v, ah0); }
      else if (k < 10){ FMA2(ai1, win2[k], v, ai1); FMA2(ah1, whn2[k], v, ah1); }
      else            { FMA2(ai2, win2[k], v, ai2); FMA2(ah2, whn2[k], v, ah2); }
    }
    float gin = hsum2(add2(add2(ai0, ai1), ai2));
    float ghn = hsum2(add2(add2(ah0, ah1), ah2));

    float n = tanhap(gin + bind + r * (ghn + bhnd));
    h = fmaf(z, h - n, n);
    hist[i * 32 + t] = h;
  }
  __syncwarp();

  // ---------------- linear head: out[j] = lW . hist[j] + lb ----------------
  float lb0 = lb[0];
  for (int j = t; j < DEC; j += 32){
    float s = lb0;
    #pragma unroll
    for (int k = 0; k < HH; k++)
      s = fmaf(lW[k], hist[j * 32 + k], s);
    out[j] = s;
  }
}

extern "C" void kernel_launch(void* const* d_in, const int* in_sizes, int n_in,
                              void* d_out, int out_size) {
  const float* x    = (const float*)d_in[0];
  const float* eWih = (const float*)d_in[1];
  const float* eWhh = (const float*)d_in[2];
  const float* ebih = (const float*)d_in[3];
  const float* ebhh = (const float*)d_in[4];
  const float* dWih = (const float*)d_in[5];
  const float* dWhh = (const float*)d_in[6];
  const float* dbih = (const float*)d_in[7];
  const float* dbhh = (const float*)d_in[8];
  const float* lW   = (const float*)d_in[9];
  const float* lb   = (const float*)d_in[10];
  float* out = (float*)d_out;

  seq2seq_kernel<<<1, 32>>>(x, eWih, eWhh, ebih, ebhh,
                            dWih, dWhh, dbih, dbhh, lW, lb, out);
}

// round 4
// speedup vs baseline: 1.3649x; 1.0179x over previous
#include <cuda_runtime.h>

typedef unsigned long long ULL;

__device__ __forceinline__ ULL pack2(float a, float b){
  ULL u; asm("mov.b64 %0, {%1, %2};" : "=l"(u) : "f"(a), "f"(b)); return u;
}
__device__ __forceinline__ float hsum2(ULL a){
  union { ULL u; float2 f; } c; c.u = a;
  return c.f.x + c.f.y;
}
#define FMA2(d, a, b, c) asm("fma.rn.f32x2 %0, %1, %2, %3;" : "=l"(d) : "l"(a), "l"(b), "l"(c))
__device__ __forceinline__ ULL add2(ULL a, ULL b){
  ULL d; asm("add.rn.f32x2 %0, %1, %2;" : "=l"(d) : "l"(a), "l"(b)); return d;
}
__device__ __forceinline__ float comb5(ULL* a){
  return hsum2(add2(add2(add2(a[0], a[1]), add2(a[2], a[3])), a[4]));
}

__device__ __forceinline__ float tanhap(float x){
  float y; asm("tanh.approx.f32 %0, %1;" : "=f"(y) : "f"(x)); return y;
}

#define LSEQ 4096
#define HH   30
#define DEC  100
#define FULLM 0xffffffffu

__global__ __launch_bounds__(32, 1) void seq2seq_kernel(
    const float* __restrict__ x,
    const float* __restrict__ eWih, const float* __restrict__ eWhh,
    const float* __restrict__ ebih, const float* __restrict__ ebhh,
    const float* __restrict__ dWih, const float* __restrict__ dWhh,
    const float* __restrict__ dbih, const float* __restrict__ dbhh,
    const float* __restrict__ lW,  const float* __restrict__ lb,
    float* __restrict__ out)
{
  __shared__ __align__(16) float xs[LSEQ + 4];
  __shared__ __align__(16) float hb[2][32];
  __shared__ __align__(16) float db[2][32];
  __shared__ __align__(16) float hist[DEC * 32];

  const int t = threadIdx.x;
  const bool act = (t < HH);

  // stage x into shared (16KB), float4
  {
    const float4* x4 = (const float4*)x;
    float4* s4 = (float4*)xs;
    #pragma unroll 4
    for (int i = t; i < LSEQ / 4; i += 32) s4[i] = x4[i];
  }
  hb[0][t] = 0.f; hb[1][t] = 0.f;

  // ------------- encoder weights -> packed registers (r/z scaled by 0.5) ----
  ULL wr2[15], wz2[15], wn2[15];
  float wir = 0.f, wiz = 0.f, win = 0.f;
  float br = 0.f, bz = 0.f, bin_e = 0.f, hbhn = 0.f;
  if (act){
    #pragma unroll
    for (int k = 0; k < 15; k++){
      wr2[k] = pack2(0.5f*eWhh[(t        ) * HH + 2*k], 0.5f*eWhh[(t        ) * HH + 2*k + 1]);
      wz2[k] = pack2(0.5f*eWhh[(t +   HH) * HH + 2*k], 0.5f*eWhh[(t +   HH) * HH + 2*k + 1]);
      wn2[k] = pack2(eWhh[(t + 2*HH) * HH + 2*k], eWhh[(t + 2*HH) * HH + 2*k + 1]);
    }
    wir = 0.5f*eWih[t]; wiz = 0.5f*eWih[t + HH]; win = eWih[t + 2*HH];
    br    = 0.5f*(ebih[t]      + ebhh[t]);
    bz    = 0.5f*(ebih[t + HH] + ebhh[t + HH]);
    bin_e = ebih[t + 2*HH];
    hbhn  = 0.5f*ebhh[t + 2*HH];
  } else {
    #pragma unroll
    for (int k = 0; k < 15; k++){ wr2[k] = 0ull; wz2[k] = 0ull; wn2[k] = 0ull; }
  }
  __syncwarp();

  // ---------------- encoder recurrence: 4096 steps ----------------
  float h = 0.f;
  float xv = xs[0];
  #pragma unroll 4
  for (int s = 0; s < LSEQ; s++){
    float* b = hb[s & 1];
    b[t] = h;                      // store first, hide work before sync
    float gxr = fmaf(xv, wir, br);
    float gxz = fmaf(xv, wiz, bz);
    float gxn = fmaf(xv, win, bin_e);
    __syncwarp();
    xv = xs[s + 1];                // prefetch next x (padded)

    // 8x LDS.128 broadcast of hidden state
    ULL p[16];
    {
      const ulonglong2* b2 = (const ulonglong2*)b;
      #pragma unroll
      for (int q = 0; q < 8; q++){ ulonglong2 u = b2[q]; p[2*q] = u.x; p[2*q+1] = u.y; }
    }

    // 5 partial accumulators per gate, filled in arrival order (depth 3)
    ULL ar[5] = {0,0,0,0,0}, az[5] = {0,0,0,0,0}, an[5] = {0,0,0,0,0};
    #pragma unroll
    for (int k = 0; k < 15; k++){
      ULL v = p[k];
      FMA2(ar[k % 5], wr2[k], v, ar[k % 5]);
      FMA2(az[k % 5], wz2[k], v, az[k % 5]);
      FMA2(an[k % 5], wn2[k], v, an[k % 5]);
    }
    float Tr = tanhap(gxr + comb5(ar));       // r = 0.5*Tr + 0.5 (folded)
    float Tz = tanhap(gxz + comb5(az));
    float gn = comb5(an);

    float z   = fmaf(0.5f, Tz, 0.5f);
    float omz = fmaf(-0.5f, Tz, 0.5f);        // 1 - z
    float zh  = z * h;                        // early, off n-chain

    float hgnb = fmaf(0.5f, gn, hbhn);        // 0.5*(gn + bhn)
    float n = tanhap(fmaf(hgnb, Tr, gxn + hgnb));  // tanh(gxn + r*(gn+bhn))
    h = fmaf(omz, n, zh);                     // (1-z)*n + z*h
  }

  // ---------------- decoder step 0 (x = h_enc, h = ones) ----------------
  float hv[HH];
  #pragma unroll
  for (int k = 0; k < HH; k++) hv[k] = __shfl_sync(FULLM, h, k);

  float brd = 0.f, bzd = 0.f, bind = 0.f, hbhnd = 0.f;
  if (act){
    brd   = 0.5f*(dbih[t]      + dbhh[t]);
    bzd   = 0.5f*(dbih[t + HH] + dbhh[t + HH]);
    bind  = dbih[t + 2*HH];
    hbhnd = 0.5f*dbhh[t + 2*HH];
  }

  if (act){
    float gir = 0.f, giz = 0.f, gin = 0.f, sr = 0.f, sz = 0.f, sn = 0.f;
    #pragma unroll
    for (int k = 0; k < HH; k++){
      float hk = hv[k];
      gir = fmaf(dWih[(t        ) * HH + k], hk, gir);
      giz = fmaf(dWih[(t +   HH) * HH + k], hk, giz);
      gin = fmaf(dWih[(t + 2*HH) * HH + k], hk, gin);
      sr += dWhh[(t        ) * HH + k];
      sz += dWhh[(t +   HH) * HH + k];
      sn += dWhh[(t + 2*HH) * HH + k];
    }
    float Tr = tanhap(0.5f*(gir + sr) + brd);
    float Tz = tanhap(0.5f*(giz + sz) + bzd);
    float z   = fmaf(0.5f, Tz, 0.5f);
    float omz = fmaf(-0.5f, Tz, 0.5f);
    float hgnb = fmaf(0.5f, sn, hbhnd);
    float n = tanhap(fmaf(hgnb, Tr, gin + bind + hgnb));
    h = fmaf(omz, n, z);   // previous h is ones
  } else {
    h = 0.f;
  }
  hist[0 * 32 + t] = h;

  // ---- decoder weights (pre-summed r/z scaled 0.5; hx==hh) -> registers ----
  ULL wsr2[15], wsz2[15], win2[15], whn2[15];
  if (act){
    #pragma unroll
    for (int k = 0; k < 15; k++){
      wsr2[k] = pack2(0.5f*(dWih[(t        ) * HH + 2*k]     + dWhh[(t        ) * HH + 2*k]),
                      0.5f*(dWih[(t        ) * HH + 2*k + 1] + dWhh[(t        ) * HH + 2*k + 1]));
      wsz2[k] = pack2(0.5f*(dWih[(t +   HH) * HH + 2*k]     + dWhh[(t +   HH) * HH + 2*k]),
                      0.5f*(dWih[(t +   HH) * HH + 2*k + 1] + dWhh[(t +   HH) * HH + 2*k + 1]));
      win2[k] = pack2(dWih[(t + 2*HH) * HH + 2*k], dWih[(t + 2*HH) * HH + 2*k + 1]);
      whn2[k] = pack2(dWhh[(t + 2*HH) * HH + 2*k], dWhh[(t + 2*HH) * HH + 2*k + 1]);
    }
  } else {
    #pragma unroll
    for (int k = 0; k < 15; k++){ wsr2[k]=0ull; wsz2[k]=0ull; win2[k]=0ull; whn2[k]=0ull; }
  }
  db[0][t] = 0.f; db[1][t] = 0.f;

  // ---------------- decoder steps 1..99 (hx == hh == h) ----------------
  for (int i = 1; i < DEC; i++){
    float* b = db[i & 1];
    b[t] = h;
    __syncwarp();
    ULL p[16];
    {
      const ulonglong2* b2 = (const ulonglong2*)b;
      #pragma unroll
      for (int q = 0; q < 8; q++){ ulonglong2 u = b2[q]; p[2*q] = u.x; p[2*q+1] = u.y; }
    }
    ULL ar[5] = {0,0,0,0,0}, az[5] = {0,0,0,0,0};
    ULL ai[5] = {0,0,0,0,0}, ah[5] = {0,0,0,0,0};
    #pragma unroll
    for (int k = 0; k < 15; k++){
      ULL v = p[k];
      FMA2(ar[k % 5], wsr2[k], v, ar[k % 5]);
      FMA2(az[k % 5], wsz2[k], v, az[k % 5]);
      FMA2(ai[k % 5], win2[k], v, ai[k % 5]);
      FMA2(ah[k % 5], whn2[k], v, ah[k % 5]);
    }
    float Tr = tanhap(comb5(ar) + brd);
    float Tz = tanhap(comb5(az) + bzd);
    float gin = comb5(ai);
    float ghn = comb5(ah);

    float z   = fmaf(0.5f, Tz, 0.5f);
    float omz = fmaf(-0.5f, Tz, 0.5f);
    float zh  = z * h;
    float hgnb = fmaf(0.5f, ghn, hbhnd);
    float n = tanhap(fmaf(hgnb, Tr, gin + bind + hgnb));
    h = fmaf(omz, n, zh);
    hist[i * 32 + t] = h;
  }
  __syncwarp();

  // ---------------- linear head: out[j] = lW . hist[j] + lb ----------------
  float lb0 = lb[0];
  for (int j = t; j < DEC; j += 32){
    float s = lb0;
    #pragma unroll
    for (int k = 0; k < HH; k++)
      s = fmaf(lW[k], hist[j * 32 + k], s);
    out[j] = s;
  }
}

extern "C" void kernel_launch(void* const* d_in, const int* in_sizes, int n_in,
                              void* d_out, int out_size) {
  const float* x    = (const float*)d_in[0];
  const float* eWih = (const float*)d_in[1];
  const float* eWhh = (const float*)d_in[2];
  const float* ebih = (const float*)d_in[3];
  const float* ebhh = (const float*)d_in[4];
  const float* dWih = (const float*)d_in[5];
  const float* dWhh = (const float*)d_in[6];
  const float* dbih = (const float*)d_in[7];
  const float* dbhh = (const float*)d_in[8];
  const float* lW   = (const float*)d_in[9];
  const float* lb   = (const float*)d_in[10];
  float* out = (float*)d_out;

  seq2seq_kernel<<<1, 32>>>(x, eWih, eWhh, ebih, ebhh,
                            dWih, dWhh, dbih, dbhh, lW, lb, out);
}